// round 4
// baseline (speedup 1.0000x reference)
#include <cuda_runtime.h>
#include <cuda_bf16.h>

#define S_LEN 6
#define E_DIM 256
#define NH    8
#define HD    32
#define HW    4096   // 64*64
#define B_MAX 16
#define BSE   (B_MAX * S_LEN * E_DIM)

// Scratch (no cudaMalloc allowed)
__device__ float g_buf[BSE];          // pooled + pos
__device__ float og_buf[BSE];         // out projection

// -------------------------------------------------------------------------
// Kernel 1: global spatial mean over 64x64 + temporal_pos  -> g[b,s,e]
// -------------------------------------------------------------------------
__global__ void __launch_bounds__(256) pool_kernel(
    const float* __restrict__ ff, const float* __restrict__ tpos, int total)
{
    int idx = blockIdx.x;                 // b*S*E + s*E + e
    if (idx >= total) return;
    const float4* p = reinterpret_cast<const float4*>(ff + (size_t)idx * HW);

    float sum = 0.f;
#pragma unroll
    for (int i = 0; i < 4; i++) {
        float4 v = __ldcs(&p[threadIdx.x + i * 256]);
        sum += (v.x + v.y) + (v.z + v.w);
    }
#pragma unroll
    for (int off = 16; off > 0; off >>= 1)
        sum += __shfl_xor_sync(0xFFFFFFFFu, sum, off);

    __shared__ float wsum[8];
    int lane = threadIdx.x & 31, wid = threadIdx.x >> 5;
    if (lane == 0) wsum[wid] = sum;
    __syncthreads();
    if (threadIdx.x == 0) {
        float tot = 0.f;
#pragma unroll
        for (int w = 0; w < 8; w++) tot += wsum[w];
        int s = (idx / E_DIM) % S_LEN;
        int e = idx % E_DIM;
        g_buf[idx] = tot * (1.0f / HW) + tpos[s * E_DIM + e];
    }
}

// -------------------------------------------------------------------------
// Kernel 2: fully fused MHA per batch. One block per batch, 256 threads.
// Dot products: 8-lane groups, ILP=8 float4 loads, 3-shuffle reduce.
// -------------------------------------------------------------------------
__global__ void __launch_bounds__(256) mha_kernel(
    const float* __restrict__ Wq, const float* __restrict__ bq,
    const float* __restrict__ Wk, const float* __restrict__ bk,
    const float* __restrict__ Wv, const float* __restrict__ bv,
    const float* __restrict__ Wo, const float* __restrict__ bo,
    float* __restrict__ attn_out, int write_attn)
{
    int b = blockIdx.x;
    int tid = threadIdx.x;
    int group = tid >> 3;                 // 0..31
    int lane8 = tid & 7;                  // 0..7

    __shared__ float sg[S_LEN][E_DIM];
    __shared__ float sq[S_LEN][E_DIM];
    __shared__ float sk[S_LEN][E_DIM];
    __shared__ float sv[S_LEN][E_DIM];
    __shared__ float sat[S_LEN][E_DIM];
    __shared__ float sc[NH][S_LEN][S_LEN];

    // load g[b]
    for (int i = tid; i < S_LEN * E_DIM; i += 256)
        sg[i / E_DIM][i % E_DIM] = g_buf[b * S_LEN * E_DIM + i];
    __syncthreads();

    // ---- QKV: 1536 (s,e) outputs, 32 groups -> 48 iterations each ----
#pragma unroll 2
    for (int p = group; p < S_LEN * E_DIM; p += 32) {
        int s = p >> 8, e = p & 255;
        const float4* wq = reinterpret_cast<const float4*>(Wq + e * E_DIM);
        const float4* wk = reinterpret_cast<const float4*>(Wk + e * E_DIM);
        const float4* wv = reinterpret_cast<const float4*>(Wv + e * E_DIM);
        const float4* gv = reinterpret_cast<const float4*>(&sg[s][0]);
        float aq = 0.f, ak = 0.f, av = 0.f;
#pragma unroll
        for (int kk = 0; kk < 8; kk++) {
            int j = lane8 + 8 * kk;
            float4 g4 = gv[j];
            float4 q4 = wq[j];
            float4 k4 = wk[j];
            float4 v4 = wv[j];
            aq += g4.x * q4.x + g4.y * q4.y + g4.z * q4.z + g4.w * q4.w;
            ak += g4.x * k4.x + g4.y * k4.y + g4.z * k4.z + g4.w * k4.w;
            av += g4.x * v4.x + g4.y * v4.y + g4.z * v4.z + g4.w * v4.w;
        }
#pragma unroll
        for (int off = 4; off > 0; off >>= 1) {
            aq += __shfl_xor_sync(0xFFFFFFFFu, aq, off);
            ak += __shfl_xor_sync(0xFFFFFFFFu, ak, off);
            av += __shfl_xor_sync(0xFFFFFFFFu, av, off);
        }
        if (lane8 == 0) {
            sq[s][e] = aq + bq[e];
            sk[s][e] = ak + bk[e];
            sv[s][e] = av + bv[e];
        }
    }
    __syncthreads();

    // ---- causal softmax per (h,s) row: 48 rows, one thread each ----
    if (tid < NH * S_LEN) {
        int h = tid / S_LEN, s = tid % S_LEN;
        float row[S_LEN];
        const float scale = 0.17677669529663687f;  // 1/sqrt(32)
        float mx = -1e30f;
        for (int t = 0; t <= s; t++) {
            float d = 0.f;
#pragma unroll
            for (int j = 0; j < HD; j++)
                d += sq[s][h * HD + j] * sk[t][h * HD + j];
            d *= scale;
            row[t] = d;
            mx = fmaxf(mx, d);
        }
        float den = 0.f;
        for (int t = 0; t <= s; t++) { row[t] = __expf(row[t] - mx); den += row[t]; }
        float inv = 1.f / den;
#pragma unroll
        for (int t = 0; t < S_LEN; t++)
            sc[h][s][t] = (t <= s) ? row[t] * inv : 0.f;
    }
    __syncthreads();

    if (write_attn) {
        const float* scp = &sc[0][0][0];
        for (int i = tid; i < NH * S_LEN * S_LEN; i += 256)
            attn_out[b * NH * S_LEN * S_LEN + i] = scp[i];
    }

    // ---- attended[s][e] = sum_t sc[h][s][t] * v[t][e] ----
    for (int i = tid; i < S_LEN * E_DIM; i += 256) {
        int s = i / E_DIM, e = i % E_DIM;
        int h = e / HD;
        float a = 0.f;
        for (int t = 0; t <= s; t++)
            a += sc[h][s][t] * sv[t][e];
        sat[s][e] = a;
    }
    __syncthreads();

    // ---- output projection: og[s][e] = sat[s] . Wo_row[e] + bo[e] ----
#pragma unroll 2
    for (int p = group; p < S_LEN * E_DIM; p += 32) {
        int s = p >> 8, e = p & 255;
        const float4* wo = reinterpret_cast<const float4*>(Wo + e * E_DIM);
        const float4* arow = reinterpret_cast<const float4*>(&sat[s][0]);
        float acc = 0.f;
#pragma unroll
        for (int kk = 0; kk < 8; kk++) {
            int j = lane8 + 8 * kk;
            float4 a4 = arow[j];
            float4 w4 = wo[j];
            acc += a4.x * w4.x + a4.y * w4.y + a4.z * w4.z + a4.w * w4.w;
        }
#pragma unroll
        for (int off = 4; off > 0; off >>= 1)
            acc += __shfl_xor_sync(0xFFFFFFFFu, acc, off);
        if (lane8 == 0)
            og_buf[(b * S_LEN + s) * E_DIM + e] = acc + bo[e];
    }
}

// -------------------------------------------------------------------------
// Kernel 3: cross[b,s,e,h,w] = ff[b,s,e,h,w] + out_g[b,s,e]
// -------------------------------------------------------------------------
__global__ void __launch_bounds__(256) add_kernel(
    const float* __restrict__ ff, float* __restrict__ out, int total)
{
    int idx = blockIdx.x;
    if (idx >= total) return;
    float add = og_buf[idx];
    const float4* p = reinterpret_cast<const float4*>(ff + (size_t)idx * HW);
    float4* o = reinterpret_cast<float4*>(out + (size_t)idx * HW);
#pragma unroll
    for (int i = 0; i < 4; i++) {
        float4 v = __ldcs(&p[threadIdx.x + i * 256]);
        v.x += add; v.y += add; v.z += add; v.w += add;
        __stcs(&o[threadIdx.x + i * 256], v);
    }
}

extern "C" void kernel_launch(void* const* d_in, const int* in_sizes, int n_in,
                              void* d_out, int out_size)
{
    const float* ff   = (const float*)d_in[0];
    const float* Wq   = (const float*)d_in[1];
    const float* bq   = (const float*)d_in[2];
    const float* Wk   = (const float*)d_in[3];
    const float* bk   = (const float*)d_in[4];
    const float* Wv   = (const float*)d_in[5];
    const float* bv   = (const float*)d_in[6];
    const float* Wo   = (const float*)d_in[7];
    const float* bo   = (const float*)d_in[8];
    const float* tpos = (const float*)d_in[9];

    int ff_elems = in_sizes[0];                       // B*S*E*H*W
    int B = ff_elems / (S_LEN * E_DIM * HW);          // 16
    int slices = B * S_LEN * E_DIM;                   // 24576

    float* cross = (float*)d_out;
    int attn_elems = B * NH * S_LEN * S_LEN;          // 4608
    int write_attn = (out_size >= ff_elems + attn_elems) ? 1 : 0;
    float* attn_out = cross + ff_elems;

    pool_kernel<<<slices, 256>>>(ff, tpos, slices);
    mha_kernel<<<B, 256>>>(Wq, bq, Wk, bk, Wv, bv, Wo, bo, attn_out, write_attn);
    add_kernel<<<slices, 256>>>(ff, cross, slices);
}

// round 5
// speedup vs baseline: 1.1264x; 1.1264x over previous
#include <cuda_runtime.h>
#include <cuda_bf16.h>

#define S_LEN 6
#define E_DIM 256
#define NH    8
#define HD    32
#define HW    4096   // 64*64
#define B_MAX 16
#define BSE   (B_MAX * S_LEN * E_DIM)

// Scratch (no cudaMalloc allowed)
__device__ float g_buf[BSE];
__device__ float q_buf[BSE];
__device__ float k_buf[BSE];
__device__ float v_buf[BSE];
__device__ float at_buf[BSE];
__device__ float og_buf[BSE];

// -------------------------------------------------------------------------
// Kernel 1: global spatial mean over 64x64 + temporal_pos  -> g[b,s,e]
// (84% DRAM — at roofline, unchanged)
// -------------------------------------------------------------------------
__global__ void __launch_bounds__(256) pool_kernel(
    const float* __restrict__ ff, const float* __restrict__ tpos, int total)
{
    int idx = blockIdx.x;                 // b*S*E + s*E + e
    if (idx >= total) return;
    const float4* p = reinterpret_cast<const float4*>(ff + (size_t)idx * HW);

    float sum = 0.f;
#pragma unroll
    for (int i = 0; i < 4; i++) {
        float4 v = __ldcs(&p[threadIdx.x + i * 256]);
        sum += (v.x + v.y) + (v.z + v.w);
    }
#pragma unroll
    for (int off = 16; off > 0; off >>= 1)
        sum += __shfl_xor_sync(0xFFFFFFFFu, sum, off);

    __shared__ float wsum[8];
    int lane = threadIdx.x & 31, wid = threadIdx.x >> 5;
    if (lane == 0) wsum[wid] = sum;
    __syncthreads();
    if (threadIdx.x == 0) {
        float tot = 0.f;
#pragma unroll
        for (int w = 0; w < 8; w++) tot += wsum[w];
        int s = (idx / E_DIM) % S_LEN;
        int e = idx % E_DIM;
        g_buf[idx] = tot * (1.0f / HW) + tpos[s * E_DIM + e];
    }
}

// -------------------------------------------------------------------------
// Kernel 2: QKV. One block per (b,s). Each warp: 4 weight rows at once
// (same W, alternating q/k/v banks by row index), 8 coalesced float4 L2
// loads in flight, then 4 butterfly reduces.
// Row index r in [0,768): r<256 -> Wq row r; <512 -> Wk; <768 -> Wv.
// -------------------------------------------------------------------------
__global__ void __launch_bounds__(256) qkv_kernel(
    const float* __restrict__ Wq, const float* __restrict__ bq,
    const float* __restrict__ Wk, const float* __restrict__ bk,
    const float* __restrict__ Wv, const float* __restrict__ bv)
{
    int bs = blockIdx.x;                  // b*S_LEN + s
    int tid = threadIdx.x;
    __shared__ float sg[E_DIM];
    sg[tid] = g_buf[bs * E_DIM + tid];
    __syncthreads();

    int warp = tid >> 5, lane = tid & 31;
    const float4* gv = reinterpret_cast<const float4*>(sg);
    float4 g0 = gv[lane];
    float4 g1 = gv[lane + 32];

    // 768 rows total, 8 warps x 4 rows = 32 rows per sweep -> 24 sweeps... no:
    // each warp takes rows [warp*4 + sweep*32 .. +3], sweeps = 768/32 = 24
#pragma unroll 1
    for (int base = warp * 4; base < 768; base += 32) {
        float acc[4];
#pragma unroll
        for (int rr = 0; rr < 4; rr++) {
            int r = base + rr;
            int which = r >> 8;
            int e = r & 255;
            const float* W = (which == 0) ? Wq : (which == 1) ? Wk : Wv;
            const float4* wrow = reinterpret_cast<const float4*>(W + e * E_DIM);
            float4 w0 = wrow[lane];
            float4 w1 = wrow[lane + 32];
            acc[rr] = w0.x * g0.x + w0.y * g0.y + w0.z * g0.z + w0.w * g0.w
                    + w1.x * g1.x + w1.y * g1.y + w1.z * g1.z + w1.w * g1.w;
        }
#pragma unroll
        for (int off = 16; off > 0; off >>= 1) {
#pragma unroll
            for (int rr = 0; rr < 4; rr++)
                acc[rr] += __shfl_xor_sync(0xFFFFFFFFu, acc[rr], off);
        }
        if (lane < 4) {
            int r = base + lane;
            int which = r >> 8;
            int e = r & 255;
            const float* bias = (which == 0) ? bq : (which == 1) ? bk : bv;
            float* dst = (which == 0) ? q_buf : (which == 1) ? k_buf : v_buf;
            dst[bs * E_DIM + e] = acc[lane] + bias[e];
        }
    }
}

// -------------------------------------------------------------------------
// Kernel 3: per-batch causal softmax + AV. One block per batch.
// -------------------------------------------------------------------------
__global__ void __launch_bounds__(256) attn_core_kernel(
    float* __restrict__ attn_out, int write_attn)
{
    int b = blockIdx.x;
    int tid = threadIdx.x;

    __shared__ float sq[S_LEN][E_DIM];
    __shared__ float sk[S_LEN][E_DIM];
    __shared__ float sv[S_LEN][E_DIM];
    __shared__ float sc[NH][S_LEN][S_LEN];

    for (int i = tid; i < S_LEN * E_DIM; i += 256) {
        sq[i / E_DIM][i % E_DIM] = q_buf[b * S_LEN * E_DIM + i];
        sk[i / E_DIM][i % E_DIM] = k_buf[b * S_LEN * E_DIM + i];
        sv[i / E_DIM][i % E_DIM] = v_buf[b * S_LEN * E_DIM + i];
    }
    __syncthreads();

    if (tid < NH * S_LEN) {
        int h = tid / S_LEN, s = tid % S_LEN;
        float row[S_LEN];
        const float scale = 0.17677669529663687f;  // 1/sqrt(32)
        float mx = -1e30f;
        for (int t = 0; t <= s; t++) {
            float d = 0.f;
#pragma unroll
            for (int j = 0; j < HD; j++)
                d += sq[s][h * HD + j] * sk[t][h * HD + j];
            d *= scale;
            row[t] = d;
            mx = fmaxf(mx, d);
        }
        float den = 0.f;
        for (int t = 0; t <= s; t++) { row[t] = __expf(row[t] - mx); den += row[t]; }
        float inv = 1.f / den;
#pragma unroll
        for (int t = 0; t < S_LEN; t++)
            sc[h][s][t] = (t <= s) ? row[t] * inv : 0.f;
    }
    __syncthreads();

    if (write_attn) {
        const float* scp = &sc[0][0][0];
        for (int i = tid; i < NH * S_LEN * S_LEN; i += 256)
            attn_out[b * NH * S_LEN * S_LEN + i] = scp[i];
    }

    for (int i = tid; i < S_LEN * E_DIM; i += 256) {
        int s = i / E_DIM, e = i % E_DIM;
        int h = e / HD;
        float a = 0.f;
        for (int t = 0; t <= s; t++)
            a += sc[h][s][t] * sv[t][e];
        at_buf[b * S_LEN * E_DIM + i] = a;
    }
}

// -------------------------------------------------------------------------
// Kernel 4: output projection. One block per (b,s); warp x 4 rows, ILP 8.
// -------------------------------------------------------------------------
__global__ void __launch_bounds__(256) oproj_kernel(
    const float* __restrict__ Wo, const float* __restrict__ bo)
{
    int bs = blockIdx.x;
    int tid = threadIdx.x;
    __shared__ float sa[E_DIM];
    sa[tid] = at_buf[bs * E_DIM + tid];
    __syncthreads();

    int warp = tid >> 5, lane = tid & 31;
    const float4* av = reinterpret_cast<const float4*>(sa);
    float4 a0 = av[lane];
    float4 a1 = av[lane + 32];

#pragma unroll 1
    for (int base = warp * 4; base < E_DIM; base += 32) {
        float acc[4];
#pragma unroll
        for (int rr = 0; rr < 4; rr++) {
            int e = base + rr;
            const float4* wrow = reinterpret_cast<const float4*>(Wo + e * E_DIM);
            float4 w0 = wrow[lane];
            float4 w1 = wrow[lane + 32];
            acc[rr] = w0.x * a0.x + w0.y * a0.y + w0.z * a0.z + w0.w * a0.w
                    + w1.x * a1.x + w1.y * a1.y + w1.z * a1.z + w1.w * a1.w;
        }
#pragma unroll
        for (int off = 16; off > 0; off >>= 1) {
#pragma unroll
            for (int rr = 0; rr < 4; rr++)
                acc[rr] += __shfl_xor_sync(0xFFFFFFFFu, acc[rr], off);
        }
        if (lane < 4) {
            int e = base + lane;
            og_buf[bs * E_DIM + e] = acc[lane] + bo[e];
        }
    }
}

// -------------------------------------------------------------------------
// Kernel 5: cross[b,s,e,h,w] = ff[b,s,e,h,w] + out_g[b,s,e]
// -------------------------------------------------------------------------
__global__ void __launch_bounds__(256) add_kernel(
    const float* __restrict__ ff, float* __restrict__ out, int total)
{
    int idx = blockIdx.x;
    if (idx >= total) return;
    float add = og_buf[idx];
    const float4* p = reinterpret_cast<const float4*>(ff + (size_t)idx * HW);
    float4* o = reinterpret_cast<float4*>(out + (size_t)idx * HW);
#pragma unroll
    for (int i = 0; i < 4; i++) {
        float4 v = __ldcs(&p[threadIdx.x + i * 256]);
        v.x += add; v.y += add; v.z += add; v.w += add;
        __stcs(&o[threadIdx.x + i * 256], v);
    }
}

extern "C" void kernel_launch(void* const* d_in, const int* in_sizes, int n_in,
                              void* d_out, int out_size)
{
    const float* ff   = (const float*)d_in[0];
    const float* Wq   = (const float*)d_in[1];
    const float* bq   = (const float*)d_in[2];
    const float* Wk   = (const float*)d_in[3];
    const float* bk   = (const float*)d_in[4];
    const float* Wv   = (const float*)d_in[5];
    const float* bv   = (const float*)d_in[6];
    const float* Wo   = (const float*)d_in[7];
    const float* bo   = (const float*)d_in[8];
    const float* tpos = (const float*)d_in[9];

    int ff_elems = in_sizes[0];                       // B*S*E*H*W
    int B = ff_elems / (S_LEN * E_DIM * HW);          // 16
    int slices = B * S_LEN * E_DIM;                   // 24576

    float* cross = (float*)d_out;
    int attn_elems = B * NH * S_LEN * S_LEN;          // 4608
    int write_attn = (out_size >= ff_elems + attn_elems) ? 1 : 0;
    float* attn_out = cross + ff_elems;

    pool_kernel<<<slices, 256>>>(ff, tpos, slices);
    qkv_kernel<<<B * S_LEN, 256>>>(Wq, bq, Wk, bk, Wv, bv);
    attn_core_kernel<<<B, 256>>>(attn_out, write_attn);
    oproj_kernel<<<B * S_LEN, 256>>>(Wo, bo);
    add_kernel<<<slices, 256>>>(ff, cross, slices);
}

// round 6
// speedup vs baseline: 1.2660x; 1.1239x over previous
#include <cuda_runtime.h>
#include <cuda_bf16.h>

#define S_LEN 6
#define E_DIM 256
#define NH    8
#define HD    32
#define HW    4096   // 64*64
#define B_MAX 16
#define BSE   (B_MAX * S_LEN * E_DIM)

// Scratch (no cudaMalloc allowed)
__device__ float g_buf[BSE];
__device__ float q_buf[BSE];
__device__ float k_buf[BSE];
__device__ float v_buf[BSE];
__device__ float og_buf[BSE];

// -------------------------------------------------------------------------
// Kernel 1: global spatial mean over 64x64 + temporal_pos  -> g[b,s,e]
// (84% DRAM — at roofline, unchanged)
// -------------------------------------------------------------------------
__global__ void __launch_bounds__(256) pool_kernel(
    const float* __restrict__ ff, const float* __restrict__ tpos, int total)
{
    int idx = blockIdx.x;                 // b*S*E + s*E + e
    if (idx >= total) return;
    const float4* p = reinterpret_cast<const float4*>(ff + (size_t)idx * HW);

    float sum = 0.f;
#pragma unroll
    for (int i = 0; i < 4; i++) {
        float4 v = __ldcs(&p[threadIdx.x + i * 256]);
        sum += (v.x + v.y) + (v.z + v.w);
    }
#pragma unroll
    for (int off = 16; off > 0; off >>= 1)
        sum += __shfl_xor_sync(0xFFFFFFFFu, sum, off);

    __shared__ float wsum[8];
    int lane = threadIdx.x & 31, wid = threadIdx.x >> 5;
    if (lane == 0) wsum[wid] = sum;
    __syncthreads();
    if (threadIdx.x == 0) {
        float tot = 0.f;
#pragma unroll
        for (int w = 0; w < 8; w++) tot += wsum[w];
        int s = (idx / E_DIM) % S_LEN;
        int e = idx % E_DIM;
        g_buf[idx] = tot * (1.0f / HW) + tpos[s * E_DIM + e];
    }
}

// -------------------------------------------------------------------------
// Kernel 2: QKV. grid = 96*4: block = (b,s) x quarter of 768 rows.
// Each warp: 4 rows at once, 8 coalesced float4 loads in flight.
// Row r: r<256 -> Wq row r; <512 -> Wk; <768 -> Wv.
// -------------------------------------------------------------------------
__global__ void __launch_bounds__(256) qkv_kernel(
    const float* __restrict__ Wq, const float* __restrict__ bq,
    const float* __restrict__ Wk, const float* __restrict__ bk,
    const float* __restrict__ Wv, const float* __restrict__ bv)
{
    int bs = blockIdx.x >> 2;             // b*S_LEN + s
    int quarter = blockIdx.x & 3;         // which 192-row chunk
    int tid = threadIdx.x;
    __shared__ float sg[E_DIM];
    sg[tid] = g_buf[bs * E_DIM + tid];
    __syncthreads();

    int warp = tid >> 5, lane = tid & 31;
    const float4* gv = reinterpret_cast<const float4*>(sg);
    float4 g0 = gv[lane];
    float4 g1 = gv[lane + 32];

    int row_lo = quarter * 192;
    int row_hi = row_lo + 192;
#pragma unroll 1
    for (int base = row_lo + warp * 4; base < row_hi; base += 32) {
        float acc[4];
#pragma unroll
        for (int rr = 0; rr < 4; rr++) {
            int r = base + rr;
            int which = r >> 8;
            int e = r & 255;
            const float* W = (which == 0) ? Wq : (which == 1) ? Wk : Wv;
            const float4* wrow = reinterpret_cast<const float4*>(W + e * E_DIM);
            float4 w0 = wrow[lane];
            float4 w1 = wrow[lane + 32];
            acc[rr] = w0.x * g0.x + w0.y * g0.y + w0.z * g0.z + w0.w * g0.w
                    + w1.x * g1.x + w1.y * g1.y + w1.z * g1.z + w1.w * g1.w;
        }
#pragma unroll
        for (int off = 16; off > 0; off >>= 1) {
#pragma unroll
            for (int rr = 0; rr < 4; rr++)
                acc[rr] += __shfl_xor_sync(0xFFFFFFFFu, acc[rr], off);
        }
        if (lane < 4) {
            int r = base + lane;
            int which = r >> 8;
            int e = r & 255;
            const float* bias = (which == 0) ? bq : (which == 1) ? bk : bv;
            float* dst = (which == 0) ? q_buf : (which == 1) ? k_buf : v_buf;
            dst[bs * E_DIM + e] = acc[lane] + bias[e];
        }
    }
}

// -------------------------------------------------------------------------
// Kernel 3: fused softmax + AV + output projection.
// grid = 96*2: block = (b,s) x half of the 256 Wo rows.
// Softmax/attended recomputed per block (tiny); Wo sweep split for occupancy.
// -------------------------------------------------------------------------
__global__ void __launch_bounds__(256) attnproj_kernel(
    const float* __restrict__ Wo, const float* __restrict__ bo,
    float* __restrict__ attn_out, int write_attn)
{
    int bs = blockIdx.x >> 1;             // b*S_LEN + s
    int half = blockIdx.x & 1;
    int b = bs / S_LEN, s = bs % S_LEN;
    int tid = threadIdx.x;

    __shared__ float sq[E_DIM];
    __shared__ float sk[S_LEN][E_DIM];
    __shared__ float sv[S_LEN][E_DIM];
    __shared__ float sc[NH][S_LEN];
    __shared__ float sat[E_DIM];

    // load q[b,s], k[b,*], v[b,*]
    sq[tid] = q_buf[bs * E_DIM + tid];
    for (int i = tid; i < S_LEN * E_DIM; i += 256) {
        sk[i / E_DIM][i % E_DIM] = k_buf[b * S_LEN * E_DIM + i];
        sv[i / E_DIM][i % E_DIM] = v_buf[b * S_LEN * E_DIM + i];
    }
    __syncthreads();

    // softmax row for this s, one thread per head
    if (tid < NH) {
        int h = tid;
        float row[S_LEN];
        const float scale = 0.17677669529663687f;  // 1/sqrt(32)
        float mx = -1e30f;
        for (int t = 0; t <= s; t++) {
            float d = 0.f;
#pragma unroll
            for (int j = 0; j < HD; j++)
                d += sq[h * HD + j] * sk[t][h * HD + j];
            d *= scale;
            row[t] = d;
            mx = fmaxf(mx, d);
        }
        float den = 0.f;
        for (int t = 0; t <= s; t++) { row[t] = __expf(row[t] - mx); den += row[t]; }
        float inv = 1.f / den;
#pragma unroll
        for (int t = 0; t < S_LEN; t++)
            sc[h][t] = (t <= s) ? row[t] * inv : 0.f;
    }
    __syncthreads();

    // write attn [b,h,s,t] once (from half 0)
    if (write_attn && half == 0 && tid < NH * S_LEN) {
        int h = tid / S_LEN, t = tid % S_LEN;
        attn_out[((b * NH + h) * S_LEN + s) * S_LEN + t] = sc[h][t];
    }

    // attended[e] = sum_t sc[h][t] * v[t][e]
    {
        int e = tid, h = e / HD;
        float a = 0.f;
        for (int t = 0; t <= s; t++)
            a += sc[h][t] * sv[t][e];
        sat[e] = a;
    }
    __syncthreads();

    // output projection over this block's half of e_out rows
    int warp = tid >> 5, lane = tid & 31;
    const float4* av = reinterpret_cast<const float4*>(sat);
    float4 a0 = av[lane];
    float4 a1 = av[lane + 32];

    int row_lo = half * 128;
    int row_hi = row_lo + 128;
#pragma unroll 1
    for (int base = row_lo + warp * 4; base < row_hi; base += 32) {
        float acc[4];
#pragma unroll
        for (int rr = 0; rr < 4; rr++) {
            int e = base + rr;
            const float4* wrow = reinterpret_cast<const float4*>(Wo + e * E_DIM);
            float4 w0 = wrow[lane];
            float4 w1 = wrow[lane + 32];
            acc[rr] = w0.x * a0.x + w0.y * a0.y + w0.z * a0.z + w0.w * a0.w
                    + w1.x * a1.x + w1.y * a1.y + w1.z * a1.z + w1.w * a1.w;
        }
#pragma unroll
        for (int off = 16; off > 0; off >>= 1) {
#pragma unroll
            for (int rr = 0; rr < 4; rr++)
                acc[rr] += __shfl_xor_sync(0xFFFFFFFFu, acc[rr], off);
        }
        if (lane < 4) {
            int e = base + lane;
            og_buf[bs * E_DIM + e] = acc[lane] + bo[e];
        }
    }
}

// -------------------------------------------------------------------------
// Kernel 4: cross[b,s,e,h,w] = ff[b,s,e,h,w] + out_g[b,s,e]
// -------------------------------------------------------------------------
__global__ void __launch_bounds__(256) add_kernel(
    const float* __restrict__ ff, float* __restrict__ out, int total)
{
    int idx = blockIdx.x;
    if (idx >= total) return;
    float add = og_buf[idx];
    const float4* p = reinterpret_cast<const float4*>(ff + (size_t)idx * HW);
    float4* o = reinterpret_cast<float4*>(out + (size_t)idx * HW);
#pragma unroll
    for (int i = 0; i < 4; i++) {
        float4 v = __ldcs(&p[threadIdx.x + i * 256]);
        v.x += add; v.y += add; v.z += add; v.w += add;
        __stcs(&o[threadIdx.x + i * 256], v);
    }
}

extern "C" void kernel_launch(void* const* d_in, const int* in_sizes, int n_in,
                              void* d_out, int out_size)
{
    const float* ff   = (const float*)d_in[0];
    const float* Wq   = (const float*)d_in[1];
    const float* bq   = (const float*)d_in[2];
    const float* Wk   = (const float*)d_in[3];
    const float* bk   = (const float*)d_in[4];
    const float* Wv   = (const float*)d_in[5];
    const float* bv   = (const float*)d_in[6];
    const float* Wo   = (const float*)d_in[7];
    const float* bo   = (const float*)d_in[8];
    const float* tpos = (const float*)d_in[9];

    int ff_elems = in_sizes[0];                       // B*S*E*H*W
    int B = ff_elems / (S_LEN * E_DIM * HW);          // 16
    int slices = B * S_LEN * E_DIM;                   // 24576

    float* cross = (float*)d_out;
    int attn_elems = B * NH * S_LEN * S_LEN;          // 4608
    int write_attn = (out_size >= ff_elems + attn_elems) ? 1 : 0;
    float* attn_out = cross + ff_elems;

    pool_kernel<<<slices, 256>>>(ff, tpos, slices);
    qkv_kernel<<<B * S_LEN * 4, 256>>>(Wq, bq, Wk, bk, Wv, bv);
    attnproj_kernel<<<B * S_LEN * 2, 256>>>(Wo, bo, attn_out, write_attn);
    add_kernel<<<slices, 256>>>(ff, cross, slices);
}